// round 1
// baseline (speedup 1.0000x reference)
#include <cuda_runtime.h>

// Problem dims
#define Bsz 4
#define Cin 8
#define Dd 48
#define Hh 128
#define Ww 160
#define HW (Hh*Ww)            // 20480
#define CH_STRIDE (Dd*HW)     // 983040
#define B_STRIDE (Cin*CH_STRIDE)

typedef unsigned long long ull;

// Fused, BN-folded, f32x2-pre-duplicated weights.
// layout: A0[16*8] @0, C0[16] @128, A1[8*16] @144, C1[8] @272, W2[8] @280, B2 @288
__device__ ull g_fw[289];

__device__ __forceinline__ ull pack2same(float f) {
    unsigned u = __float_as_uint(f);
    return (((ull)u) << 32) | (ull)u;
}

__global__ void pw_setup_kernel(const float* __restrict__ w0, const float* __restrict__ g0,
                                const float* __restrict__ b0, const float* __restrict__ m0,
                                const float* __restrict__ v0,
                                const float* __restrict__ w1, const float* __restrict__ g1,
                                const float* __restrict__ b1, const float* __restrict__ m1,
                                const float* __restrict__ v1,
                                const float* __restrict__ w2, const float* __restrict__ b2) {
    int t = threadIdx.x;
    if (t < 16) {
        float s = g0[t] * rsqrtf(v0[t] + 1e-5f);
        #pragma unroll
        for (int c = 0; c < 8; c++) g_fw[t * 8 + c] = pack2same(w0[t * 8 + c] * s);
        g_fw[128 + t] = pack2same(b0[t] - m0[t] * s);
    } else if (t < 24) {
        int o = t - 16;
        float s = g1[o] * rsqrtf(v1[o] + 1e-5f);
        #pragma unroll
        for (int c = 0; c < 16; c++) g_fw[144 + o * 16 + c] = pack2same(w1[o * 16 + c] * s);
        g_fw[272 + o] = pack2same(b1[o] - m1[o] * s);
    } else if (t < 32) {
        g_fw[280 + (t - 24)] = pack2same(w2[t - 24]);
    } else if (t == 32) {
        g_fw[288] = pack2same(b2[0]);
    }
}

// ---- packed f32x2 helpers (Blackwell: ptxas never auto-fuses, must use PTX) ----
__device__ __forceinline__ ull ffma2(ull a, ull b, ull c) {
    ull d;
    asm("fma.rn.f32x2 %0, %1, %2, %3;" : "=l"(d) : "l"(a), "l"(b), "l"(c));
    return d;
}
__device__ __forceinline__ float lo_f(ull a) { return __uint_as_float((unsigned)a); }
__device__ __forceinline__ float hi_f(ull a) { return __uint_as_float((unsigned)(a >> 32)); }
__device__ __forceinline__ ull mk2(float lo, float hi) {
    return (((ull)__float_as_uint(hi)) << 32) | (ull)__float_as_uint(lo);
}
__device__ __forceinline__ ull relu2(ull a) {
    return mk2(fmaxf(lo_f(a), 0.0f), fmaxf(hi_f(a), 0.0f));
}
__device__ __forceinline__ ull max2(ull a, ull b) {
    return mk2(fmaxf(lo_f(a), lo_f(b)), fmaxf(hi_f(a), hi_f(b)));
}

// Compute the fused MLP for one f32x2 pair (2 adjacent-w voxels), return packed s.
__device__ __forceinline__ ull mlp_pair(const ull* __restrict__ sw, const ull x[8]) {
    ull h[16];
    #pragma unroll
    for (int o = 0; o < 16; o++) {
        ull acc = sw[128 + o];
        #pragma unroll
        for (int c = 0; c < 8; c++) acc = ffma2(sw[o * 8 + c], x[c], acc);
        h[o] = relu2(acc);
    }
    ull z[8];
    #pragma unroll
    for (int o = 0; o < 8; o++) {
        ull acc = sw[272 + o];
        #pragma unroll
        for (int c = 0; c < 16; c++) acc = ffma2(sw[144 + o * 16 + c], h[c], acc);
        z[o] = relu2(acc);
    }
    ull s = sw[288];
    #pragma unroll
    for (int c = 0; c < 8; c++) s = ffma2(sw[280 + c], z[c], s);
    return s;
}

// One thread = one (b, h, w-pair). Loops d in steps of 2 (4 voxels / iter).
// max over d is taken on the pre-sigmoid logit (sigmoid monotone), 1 sigmoid at end.
__global__ __launch_bounds__(64) void pw_main_kernel(const float* __restrict__ x,
                                                     float* __restrict__ out) {
    __shared__ ull sw[289];
    for (int i = threadIdx.x; i < 289; i += 64) sw[i] = g_fw[i];
    __syncthreads();

    int t  = blockIdx.x * 64 + threadIdx.x;   // 0 .. 40959
    int wp = t % 80;
    int h  = (t / 80) % Hh;
    int b  = t / (80 * Hh);

    const float* base = x + (size_t)b * B_STRIDE + h * Ww + wp * 2;

    ull mx = pack2same(-3.0e38f);

    for (int d = 0; d < Dd; d += 2) {
        ull xa[8], xb[8];
        #pragma unroll
        for (int c = 0; c < 8; c++) {
            const float* p = base + c * CH_STRIDE + d * HW;
            xa[c] = *(const ull*)p;          // 8B-aligned: (h*160 + 2*wp) is even
            xb[c] = *(const ull*)(p + HW);
        }
        ull sA = mlp_pair(sw, xa);
        ull sB = mlp_pair(sw, xb);
        mx = max2(mx, max2(sA, sB));
    }

    float r0 = 1.0f / (1.0f + __expf(-lo_f(mx)));
    float r1 = 1.0f / (1.0f + __expf(-hi_f(mx)));
    float2* po = (float2*)(out + (size_t)b * HW + h * Ww + wp * 2);
    *po = make_float2(r0, r1);
}

extern "C" void kernel_launch(void* const* d_in, const int* in_sizes, int n_in,
                              void* d_out, int out_size) {
    const float* x1 = (const float*)d_in[0];
    const float* w0 = (const float*)d_in[1];
    const float* g0 = (const float*)d_in[2];
    const float* b0 = (const float*)d_in[3];
    const float* m0 = (const float*)d_in[4];
    const float* v0 = (const float*)d_in[5];
    const float* w1 = (const float*)d_in[6];
    const float* g1 = (const float*)d_in[7];
    const float* b1 = (const float*)d_in[8];
    const float* m1 = (const float*)d_in[9];
    const float* v1 = (const float*)d_in[10];
    const float* w2 = (const float*)d_in[11];
    const float* b2 = (const float*)d_in[12];
    float* out = (float*)d_out;

    pw_setup_kernel<<<1, 64>>>(w0, g0, b0, m0, v0, w1, g1, b1, m1, v1, w2, b2);

    // 4 * 128 * 80 = 40960 threads, 64/block -> 640 blocks
    pw_main_kernel<<<640, 64>>>(x1, out);
}

// round 2
// speedup vs baseline: 10.0335x; 10.0335x over previous
#include <cuda_runtime.h>

// Problem dims
#define Bsz 4
#define Cin 8
#define Dd 48
#define Hh 128
#define Ww 160
#define HW (Hh*Ww)            // 20480
#define CH_STRIDE (Dd*HW)     // 983040
#define B_STRIDE (Cin*CH_STRIDE)

typedef unsigned long long ull;

// Fused, BN-folded, f32x2-pre-duplicated weights.
// layout: A0[16*8] @0, C0[16] @128, A1[8*16] @144, C1[8] @272, W2[8] @280, B2 @288
__device__ ull g_fw[289];

__device__ __forceinline__ ull pack2same(float f) {
    unsigned u = __float_as_uint(f);
    return (((ull)u) << 32) | (ull)u;
}

__global__ void pw_setup_kernel(const float* __restrict__ w0, const float* __restrict__ g0,
                                const float* __restrict__ b0, const float* __restrict__ m0,
                                const float* __restrict__ v0,
                                const float* __restrict__ w1, const float* __restrict__ g1,
                                const float* __restrict__ b1, const float* __restrict__ m1,
                                const float* __restrict__ v1,
                                const float* __restrict__ w2, const float* __restrict__ b2) {
    int t = threadIdx.x;
    if (t < 16) {
        float s = g0[t] * rsqrtf(v0[t] + 1e-5f);
        #pragma unroll
        for (int c = 0; c < 8; c++) g_fw[t * 8 + c] = pack2same(w0[t * 8 + c] * s);
        g_fw[128 + t] = pack2same(b0[t] - m0[t] * s);
    } else if (t < 24) {
        int o = t - 16;
        float s = g1[o] * rsqrtf(v1[o] + 1e-5f);
        #pragma unroll
        for (int c = 0; c < 16; c++) g_fw[144 + o * 16 + c] = pack2same(w1[o * 16 + c] * s);
        g_fw[272 + o] = pack2same(b1[o] - m1[o] * s);
    } else if (t < 32) {
        g_fw[280 + (t - 24)] = pack2same(w2[t - 24]);
    } else if (t == 32) {
        g_fw[288] = pack2same(b2[0]);
    }
}

// ---- packed f32x2 helpers (Blackwell: ptxas never auto-fuses; must use PTX) ----
__device__ __forceinline__ ull ffma2(ull a, ull b, ull c) {
    ull d;
    asm("fma.rn.f32x2 %0, %1, %2, %3;" : "=l"(d) : "l"(a), "l"(b), "l"(c));
    return d;
}
__device__ __forceinline__ float lo_f(ull a) { return __uint_as_float((unsigned)a); }
__device__ __forceinline__ float hi_f(ull a) { return __uint_as_float((unsigned)(a >> 32)); }
__device__ __forceinline__ ull mk2(float lo, float hi) {
    return (((ull)__float_as_uint(hi)) << 32) | (ull)__float_as_uint(lo);
}
__device__ __forceinline__ ull relu2(ull a) {
    return mk2(fmaxf(lo_f(a), 0.0f), fmaxf(hi_f(a), 0.0f));
}
__device__ __forceinline__ ull max2(ull a, ull b) {
    return mk2(fmaxf(lo_f(a), lo_f(b)), fmaxf(hi_f(a), hi_f(b)));
}

// Block = 128 threads. Warp w (=ds) owns depth slice [12w, 12w+12).
// Lane = one of 32 consecutive w-pairs -> all LDG/STG perfectly coalesced.
// max over d on the pre-sigmoid logit (sigmoid monotone); smem max-reduce across
// the 4 depth slices; warp 0 applies 1 sigmoid and stores.
__global__ __launch_bounds__(128, 1) void pw_main_kernel(const float* __restrict__ x,
                                                         float* __restrict__ out) {
    __shared__ ull sw[289];
    __shared__ ull red[128];
    for (int i = threadIdx.x; i < 289; i += 128) sw[i] = g_fw[i];
    __syncthreads();

    const int lane = threadIdx.x & 31;
    const int ds   = threadIdx.x >> 5;           // 0..3
    const int pidx = blockIdx.x * 32 + lane;     // global pair index, 0..40959
    const int wp   = pidx % 80;
    const int hh   = (pidx / 80) & (Hh - 1);
    const int bb   = pidx / (80 * Hh);

    const float* base = x + (size_t)bb * B_STRIDE + (size_t)hh * Ww + wp * 2
                          + (size_t)ds * 12 * HW;

    // prefetch d=0
    ull xv[8];
    #pragma unroll
    for (int c = 0; c < 8; c++)
        xv[c] = *(const ull*)(base + (size_t)c * CH_STRIDE);

    ull mx = pack2same(-3.0e38f);

    #pragma unroll
    for (int d = 0; d < 12; d++) {
        ull xn[8];
        if (d < 11) {
            #pragma unroll
            for (int c = 0; c < 8; c++)
                xn[c] = *(const ull*)(base + (size_t)c * CH_STRIDE + (size_t)(d + 1) * HW);
        }

        // layer 0: 8 -> 16 (BN folded), ReLU
        ull hreg[16];
        #pragma unroll
        for (int o = 0; o < 16; o++) {
            ull acc = sw[128 + o];
            #pragma unroll
            for (int c = 0; c < 8; c++) acc = ffma2(sw[o * 8 + c], xv[c], acc);
            hreg[o] = relu2(acc);
        }

        // layer 1 (16 -> 8, BN folded, ReLU) fused with layer 2 (8 -> 1)
        ull s = sw[288];
        #pragma unroll
        for (int o = 0; o < 8; o++) {
            ull acc = sw[272 + o];
            #pragma unroll
            for (int c = 0; c < 16; c++) acc = ffma2(sw[144 + o * 16 + c], hreg[c], acc);
            s = ffma2(sw[280 + o], relu2(acc), s);
        }

        mx = max2(mx, s);

        #pragma unroll
        for (int c = 0; c < 8; c++) xv[c] = xn[c];
    }

    red[threadIdx.x] = mx;
    __syncthreads();

    if (threadIdx.x < 32) {
        ull m = max2(max2(red[lane], red[lane + 32]),
                     max2(red[lane + 64], red[lane + 96]));
        float r0 = 1.0f / (1.0f + __expf(-lo_f(m)));
        float r1 = 1.0f / (1.0f + __expf(-hi_f(m)));
        float2* po = (float2*)(out + (size_t)bb * HW + (size_t)hh * Ww + wp * 2);
        *po = make_float2(r0, r1);
    }
}

extern "C" void kernel_launch(void* const* d_in, const int* in_sizes, int n_in,
                              void* d_out, int out_size) {
    const float* x1 = (const float*)d_in[0];
    const float* w0 = (const float*)d_in[1];
    const float* g0 = (const float*)d_in[2];
    const float* b0 = (const float*)d_in[3];
    const float* m0 = (const float*)d_in[4];
    const float* v0 = (const float*)d_in[5];
    const float* w1 = (const float*)d_in[6];
    const float* g1 = (const float*)d_in[7];
    const float* b1 = (const float*)d_in[8];
    const float* m1 = (const float*)d_in[9];
    const float* v1 = (const float*)d_in[10];
    const float* w2 = (const float*)d_in[11];
    const float* b2 = (const float*)d_in[12];
    float* out = (float*)d_out;

    pw_setup_kernel<<<1, 64>>>(w0, g0, b0, m0, v0, w1, g1, b1, m1, v1, w2, b2);

    // 40960 pairs / 32 per block = 1280 blocks, 128 threads each
    pw_main_kernel<<<1280, 128>>>(x1, out);
}